// round 3
// baseline (speedup 1.0000x reference)
#include <cuda_runtime.h>
#include <cstdint>

// B=131072, IN_DIM=256, K=16, H=2, ATTN_DIM=64
#define NB_B 131072
#define ROWS_PER_BLK 32
#define NBLOCKS (NB_B / ROWS_PER_BLK)   // 4096

// ---- shared memory layout (float offsets) ----
// Pbuf [32][516]  : P during A2/B, mixed during B/C.  Cs [32][260] overlays it in A1.
// ring 8 warps x 3 stages x 256
// qs   [32][132]  : q (tf32) between A1 and A2
// Bs   [32][36]   : streamed B-operand tile for all GEMM phases
#define PB_STRIDE 516
#define PBUF_SZ   (32 * PB_STRIDE)          // 16512
#define RING_OFF  PBUF_SZ
#define RING_SZ   (8 * 3 * 256)             // 6144
#define QS_OFF    (RING_OFF + RING_SZ)      // 22656
#define QS_STRIDE 132
#define BS_OFF    (QS_OFF + 32 * QS_STRIDE) // 26880
#define BS_STRIDE 36
#define SMEM_FLOATS (BS_OFF + 32 * BS_STRIDE) // 28032
#define SMEM_BYTES  (SMEM_FLOATS * 4)          // 112128
#define CS_STRIDE 260

// device scratch
__device__ float g_Mcat[128 * 512];   // tf32: Mcat[o][h*256+i] = sum_d Wout[o,h*128+d]*Wv[h*128+d,i]
__device__ float g_WnT[256 * 128];    // tf32: 0.125 * Wn^T   (g_WnT[j][a], a = h*64+a')

__device__ __forceinline__ float to_tf32(float x) {
    uint32_t u;
    asm("cvt.rna.tf32.f32 %0, %1;" : "=r"(u) : "f"(x));
    return __uint_as_float(u);
}

__device__ __forceinline__ void mma_tf32(float* c, const uint32_t* a, const uint32_t* b) {
    asm volatile(
        "mma.sync.aligned.m16n8k8.row.col.f32.tf32.tf32.f32 "
        "{%0,%1,%2,%3}, {%4,%5,%6,%7}, {%8,%9}, {%0,%1,%2,%3};"
        : "+f"(c[0]), "+f"(c[1]), "+f"(c[2]), "+f"(c[3])
        : "r"(a[0]), "r"(a[1]), "r"(a[2]), "r"(a[3]), "r"(b[0]), "r"(b[1]));
}

__device__ __forceinline__ void cp16(float* dst, const float* src) {
    uint32_t d = (uint32_t)__cvta_generic_to_shared(dst);
    asm volatile("cp.async.cg.shared.global [%0], [%1], 16;" :: "r"(d), "l"(src));
}
__device__ __forceinline__ void cp_commit() { asm volatile("cp.async.commit_group;"); }

// ---------------------------------------------------------------------------
// prep: Mcat = Wout_h * Wv_h (tf32) ; WnT = 0.125 * Wn^T (tf32)
// ---------------------------------------------------------------------------
__global__ void prep_kernel(const float* __restrict__ Wn, const float* __restrict__ Wv,
                            const float* __restrict__ Wout) {
    int idx = blockIdx.x * blockDim.x + threadIdx.x;
    if (idx < 128 * 512) {
        int o = idx >> 9;
        int c = idx & 511;
        int h = c >> 8;
        int i = c & 255;
        float s = 0.f;
#pragma unroll 8
        for (int d = 0; d < 128; d++)
            s += Wout[o * 256 + h * 128 + d] * Wv[(h * 128 + d) * 256 + i];
        g_Mcat[idx] = to_tf32(s);
    } else if (idx < 128 * 512 + 256 * 128) {
        int idx2 = idx - 128 * 512;
        int j = idx2 >> 7;
        int a = idx2 & 127;
        g_WnT[idx2] = to_tf32(0.125f * Wn[a * 256 + j]);
    }
}

// ---------------------------------------------------------------------------
// fused kernel: 32 rows per block, 256 threads (8 warps), 2 blocks/SM
//   A1: [q | center_out][32,256] = center[32,256] @ [Wc;Wco]^T   (tf32 mma)
//   A2: P[32,512]: per head P_h = q_h[32,64] @ WnT_h             (tf32 mma)
//   B : attention with continuous 3-stage cp.async ring; mixed overwrites P
//   C : out[:,128:256] = mixed[32,512] @ Mcat^T                  (tf32 mma)
// ---------------------------------------------------------------------------
__global__ __launch_bounds__(256, 2) void fused_kernel(
    const float* __restrict__ C, const float* __restrict__ NBp,
    const float* __restrict__ EW, const float* __restrict__ Wc,
    const float* __restrict__ Wco, float* __restrict__ out) {
    extern __shared__ float sm[];
    int tid = threadIdx.x;
    int warp = tid >> 5, lane = tid & 31;
    int rowBase = blockIdx.x * ROWS_PER_BLK;
    int warpM = warp >> 2, warpN = warp & 3;

    float* Cs   = sm;              // overlays Pbuf during A1
    float* ring = sm + RING_OFF;
    float* qs   = sm + QS_OFF;
    float* Bs   = sm + BS_OFF;

    // ---- prologue: center tile + first 3 ring stages, all cp.async ----
    for (int i = tid; i < 2048; i += 256) {            // 32x256 floats = 2048 f4
        int r = i >> 6, c4 = i & 63;
        cp16(Cs + r * CS_STRIDE + c4 * 4, C + (size_t)(rowBase + r) * 256 + c4 * 4);
    }
    cp_commit();
    {
        const float* nrow = NBp + (size_t)(rowBase + warp * 4) * 4096;
#pragma unroll
        for (int k = 0; k < 3; k++) {
            float* dst = ring + warp * 768 + k * 256 + lane * 8;
            cp16(dst, nrow + k * 256 + lane * 8);
            cp16(dst + 4, nrow + k * 256 + lane * 8 + 4);
            cp_commit();
        }
    }
    asm volatile("cp.async.wait_group 3;" ::: "memory");  // Cs done, ring in flight
    __syncthreads();

    int rr = warpM * 16 + (lane >> 2);
    int cfr = warpN * 8 + ((lane & 3) << 1);   // c-frag col within 32-chunk

    // ================= Phase A1: q + center_out =================
    for (int nc = 0; nc < 8; nc++) {
        float acc[4] = {0.f, 0.f, 0.f, 0.f};
        for (int kk = 0; kk < 256; kk += 32) {
            __syncthreads();
            {
                int r = tid >> 3, c4 = tid & 7;
                int gn = nc * 32 + r;
                const float* src = (gn < 128) ? (Wc + (size_t)gn * 256)
                                              : (Wco + (size_t)(gn - 128) * 256);
                float4 v = *(const float4*)(src + kk + c4 * 4);
                v.x = to_tf32(v.x); v.y = to_tf32(v.y); v.z = to_tf32(v.z); v.w = to_tf32(v.w);
                *(float4*)(Bs + r * BS_STRIDE + c4 * 4) = v;
            }
            __syncthreads();
#pragma unroll
            for (int k8 = 0; k8 < 4; k8++) {
                int kc = k8 * 8 + (lane & 3);
                uint32_t a[4], b[2];
                a[0] = __float_as_uint(to_tf32(Cs[rr * CS_STRIDE + kk + kc]));
                a[1] = __float_as_uint(to_tf32(Cs[(rr + 8) * CS_STRIDE + kk + kc]));
                a[2] = __float_as_uint(to_tf32(Cs[rr * CS_STRIDE + kk + kc + 4]));
                a[3] = __float_as_uint(to_tf32(Cs[(rr + 8) * CS_STRIDE + kk + kc + 4]));
                int n = warpN * 8 + (lane >> 2);
                b[0] = __float_as_uint(Bs[n * BS_STRIDE + kc]);
                b[1] = __float_as_uint(Bs[n * BS_STRIDE + kc + 4]);
                mma_tf32(acc, a, b);
            }
        }
        if (nc < 4) {     // q -> qs (store as tf32, it feeds A2's A operand)
            int qc = nc * 32 + cfr;
            qs[rr * QS_STRIDE + qc]           = to_tf32(acc[0]);
            qs[rr * QS_STRIDE + qc + 1]       = to_tf32(acc[1]);
            qs[(rr + 8) * QS_STRIDE + qc]     = to_tf32(acc[2]);
            qs[(rr + 8) * QS_STRIDE + qc + 1] = to_tf32(acc[3]);
        } else {          // center_out -> out[:, 0:128]
            int oc = (nc - 4) * 32 + cfr;
            out[(size_t)(rowBase + rr) * 256 + oc]           = acc[0];
            out[(size_t)(rowBase + rr) * 256 + oc + 1]       = acc[1];
            out[(size_t)(rowBase + rr + 8) * 256 + oc]       = acc[2];
            out[(size_t)(rowBase + rr + 8) * 256 + oc + 1]   = acc[3];
        }
    }
    __syncthreads();   // qs ready; Cs dead -> Pbuf reusable

    // ================= Phase A2: P = q @ WnT (per head, K=64) =================
    for (int h = 0; h < 2; h++) {
        for (int nc = 0; nc < 8; nc++) {
            float acc[4] = {0.f, 0.f, 0.f, 0.f};
#pragma unroll
            for (int kk = 0; kk < 64; kk += 32) {
                __syncthreads();
                {
                    int r = tid >> 3, c4 = tid & 7;
                    float4 v = *(const float4*)(g_WnT + (size_t)(nc * 32 + r) * 128 + h * 64 + kk + c4 * 4);
                    *(float4*)(Bs + r * BS_STRIDE + c4 * 4) = v;   // already tf32
                }
                __syncthreads();
#pragma unroll
                for (int k8 = 0; k8 < 4; k8++) {
                    int kc = k8 * 8 + (lane & 3);
                    uint32_t a[4], b[2];
                    a[0] = __float_as_uint(qs[rr * QS_STRIDE + h * 64 + kk + kc]);
                    a[1] = __float_as_uint(qs[(rr + 8) * QS_STRIDE + h * 64 + kk + kc]);
                    a[2] = __float_as_uint(qs[rr * QS_STRIDE + h * 64 + kk + kc + 4]);
                    a[3] = __float_as_uint(qs[(rr + 8) * QS_STRIDE + h * 64 + kk + kc + 4]);
                    int n = warpN * 8 + (lane >> 2);
                    b[0] = __float_as_uint(Bs[n * BS_STRIDE + kc]);
                    b[1] = __float_as_uint(Bs[n * BS_STRIDE + kc + 4]);
                    mma_tf32(acc, a, b);
                }
            }
            int c0 = h * 256 + nc * 32 + cfr;
            sm[rr * PB_STRIDE + c0]           = acc[0];
            sm[rr * PB_STRIDE + c0 + 1]       = acc[1];
            sm[(rr + 8) * PB_STRIDE + c0]     = acc[2];
            sm[(rr + 8) * PB_STRIDE + c0 + 1] = acc[3];
        }
    }
    __syncthreads();   // P complete

    // ================= Phase B: attention (4 rows per warp) =================
    {
        int slot = 0;
        for (int r = 0; r < 4; r++) {
            int lrow = warp * 4 + r;
            int grow = rowBase + lrow;
            float* prow = sm + lrow * PB_STRIDE;
            float4 t0 = *(const float4*)(prow + lane * 8);
            float4 t1 = *(const float4*)(prow + lane * 8 + 4);
            float4 t2 = *(const float4*)(prow + 256 + lane * 8);
            float4 t3 = *(const float4*)(prow + 256 + lane * 8 + 4);
            float P0[8] = {t0.x, t0.y, t0.z, t0.w, t1.x, t1.y, t1.z, t1.w};
            float P1[8] = {t2.x, t2.y, t2.z, t2.w, t3.x, t3.y, t3.z, t3.w};
            float ewv = (lane < 16) ? EW[(size_t)grow * 16 + lane] : 0.f;
            float acc0[8], acc1[8];
#pragma unroll
            for (int j = 0; j < 8; j++) { acc0[j] = 0.f; acc1[j] = 0.f; }
            float l0 = 0.f, l1 = 0.f;

#pragma unroll
            for (int k = 0; k < 16; k++) {
                asm volatile("cp.async.wait_group 2;" ::: "memory");
                const float* src = ring + warp * 768 + slot * 256 + lane * 8;
                float4 v0 = *(const float4*)(src);
                float4 v1 = *(const float4*)(src + 4);
                float nv[8] = {v0.x, v0.y, v0.z, v0.w, v1.x, v1.y, v1.z, v1.w};

                float s0 = 0.f, s1 = 0.f;
#pragma unroll
                for (int j = 0; j < 8; j++) { s0 += nv[j] * P0[j]; s1 += nv[j] * P1[j]; }
#pragma unroll
                for (int off = 16; off; off >>= 1) {
                    s0 += __shfl_xor_sync(0xffffffffu, s0, off);
                    s1 += __shfl_xor_sync(0xffffffffu, s1, off);
                }
                float e = __shfl_sync(0xffffffffu, ewv, k);
                float w0 = __expf(s0 + e);   // scale folded into WnT; scores bounded
                float w1 = __expf(s1 + e);
                l0 += w0; l1 += w1;
#pragma unroll
                for (int j = 0; j < 8; j++) { acc0[j] += w0 * nv[j]; acc1[j] += w1 * nv[j]; }

                int s = r * 16 + k;
                if (s + 3 < 64) {   // continuous prefetch into the slot just consumed
                    int t = s + 3;
                    const float* nsrc = NBp + (size_t)(rowBase + warp * 4 + (t >> 4)) * 4096
                                        + (t & 15) * 256 + lane * 8;
                    float* dst = ring + warp * 768 + slot * 256 + lane * 8;
                    cp16(dst, nsrc);
                    cp16(dst + 4, nsrc + 4);
                }
                cp_commit();
                slot = (slot == 2) ? 0 : slot + 1;
            }

            float i0 = 1.f / l0, i1 = 1.f / l1;
            float4 o;
            o.x = to_tf32(acc0[0] * i0); o.y = to_tf32(acc0[1] * i0);
            o.z = to_tf32(acc0[2] * i0); o.w = to_tf32(acc0[3] * i0);
            *(float4*)(prow + lane * 8) = o;
            o.x = to_tf32(acc0[4] * i0); o.y = to_tf32(acc0[5] * i0);
            o.z = to_tf32(acc0[6] * i0); o.w = to_tf32(acc0[7] * i0);
            *(float4*)(prow + lane * 8 + 4) = o;
            o.x = to_tf32(acc1[0] * i1); o.y = to_tf32(acc1[1] * i1);
            o.z = to_tf32(acc1[2] * i1); o.w = to_tf32(acc1[3] * i1);
            *(float4*)(prow + 256 + lane * 8) = o;
            o.x = to_tf32(acc1[4] * i1); o.y = to_tf32(acc1[5] * i1);
            o.z = to_tf32(acc1[6] * i1); o.w = to_tf32(acc1[7] * i1);
            *(float4*)(prow + 256 + lane * 8 + 4) = o;
        }
    }
    __syncthreads();   // mixed complete

    // ================= Phase C: out[:,128:256] = mixed @ Mcat^T =================
    for (int nc = 0; nc < 4; nc++) {
        float acc[4] = {0.f, 0.f, 0.f, 0.f};
        for (int kk = 0; kk < 512; kk += 32) {
            __syncthreads();
            {
                int r = tid >> 3, c4 = tid & 7;
                float4 v = *(const float4*)(g_Mcat + (size_t)(nc * 32 + r) * 512 + kk + c4 * 4);
                *(float4*)(Bs + r * BS_STRIDE + c4 * 4) = v;   // already tf32
            }
            __syncthreads();
#pragma unroll
            for (int k8 = 0; k8 < 4; k8++) {
                int kc = k8 * 8 + (lane & 3);
                uint32_t a[4], b[2];
                a[0] = __float_as_uint(sm[rr * PB_STRIDE + kk + kc]);
                a[1] = __float_as_uint(sm[(rr + 8) * PB_STRIDE + kk + kc]);
                a[2] = __float_as_uint(sm[rr * PB_STRIDE + kk + kc + 4]);
                a[3] = __float_as_uint(sm[(rr + 8) * PB_STRIDE + kk + kc + 4]);
                int n = warpN * 8 + (lane >> 2);
                b[0] = __float_as_uint(Bs[n * BS_STRIDE + kc]);
                b[1] = __float_as_uint(Bs[n * BS_STRIDE + kc + 4]);
                mma_tf32(acc, a, b);
            }
        }
        int oc = 128 + nc * 32 + cfr;
        out[(size_t)(rowBase + rr) * 256 + oc]           = acc[0];
        out[(size_t)(rowBase + rr) * 256 + oc + 1]       = acc[1];
        out[(size_t)(rowBase + rr + 8) * 256 + oc]       = acc[2];
        out[(size_t)(rowBase + rr + 8) * 256 + oc + 1]   = acc[3];
    }
}

// ---------------------------------------------------------------------------
extern "C" void kernel_launch(void* const* d_in, const int* in_sizes, int n_in,
                              void* d_out, int out_size) {
    const float* center   = (const float*)d_in[0];
    const float* neighbor = (const float*)d_in[1];
    const float* edge     = (const float*)d_in[2];
    const float* Wc       = (const float*)d_in[3];
    const float* Wn       = (const float*)d_in[4];
    const float* Wv       = (const float*)d_in[5];
    const float* Wout     = (const float*)d_in[6];
    const float* Wco      = (const float*)d_in[7];
    float* out = (float*)d_out;

    cudaFuncSetAttribute(fused_kernel, cudaFuncAttributeMaxDynamicSharedMemorySize, SMEM_BYTES);

    prep_kernel<<<(128 * 512 + 256 * 128 + 255) / 256, 256>>>(Wn, Wv, Wout);
    fused_kernel<<<NBLOCKS, 256, SMEM_BYTES>>>(center, neighbor, edge, Wc, Wco, out);
}

// round 4
// speedup vs baseline: 1.9468x; 1.9468x over previous
#include <cuda_runtime.h>
#include <cstdint>

// B=131072, IN_DIM=256, K=16, H=2, ATTN_DIM=64
#define NB_B 131072

// device scratch
__device__ float g_Mcat[128 * 512];          // tf32: Mcat[o][h*256+i]
__device__ float g_WnT[256 * 128];           // tf32: 0.125*Wn^T  [j][h*64+a]
__device__ float g_Q[(size_t)NB_B * 128];    // tf32: q = center @ Wc^T

__device__ __forceinline__ float to_tf32(float x) {
    uint32_t u;
    asm("cvt.rna.tf32.f32 %0, %1;" : "=r"(u) : "f"(x));
    return __uint_as_float(u);
}

__device__ __forceinline__ void mma_tf32(float* c, const uint32_t* a, const uint32_t* b) {
    asm volatile(
        "mma.sync.aligned.m16n8k8.row.col.f32.tf32.tf32.f32 "
        "{%0,%1,%2,%3}, {%4,%5,%6,%7}, {%8,%9}, {%0,%1,%2,%3};"
        : "+f"(c[0]), "+f"(c[1]), "+f"(c[2]), "+f"(c[3])
        : "r"(a[0]), "r"(a[1]), "r"(a[2]), "r"(a[3]), "r"(b[0]), "r"(b[1]));
}

__device__ __forceinline__ void cp16(float* dst, const float* src) {
    uint32_t d = (uint32_t)__cvta_generic_to_shared(dst);
    asm volatile("cp.async.cg.shared.global [%0], [%1], 16;" :: "r"(d), "l"(src));
}
__device__ __forceinline__ void cp_commit() { asm volatile("cp.async.commit_group;"); }

// ---------------------------------------------------------------------------
// prep: Mcat = Wout_h * Wv_h (tf32);  WnT = 0.125 * Wn^T (tf32)
// ---------------------------------------------------------------------------
__global__ void prep_kernel(const float* __restrict__ Wn, const float* __restrict__ Wv,
                            const float* __restrict__ Wout) {
    int idx = blockIdx.x * blockDim.x + threadIdx.x;
    if (idx < 128 * 512) {
        int o = idx >> 9;
        int c = idx & 511;
        int h = c >> 8;
        int i = c & 255;
        float s = 0.f;
#pragma unroll 8
        for (int d = 0; d < 128; d++)
            s += Wout[o * 256 + h * 128 + d] * Wv[(h * 128 + d) * 256 + i];
        g_Mcat[idx] = to_tf32(s);
    } else if (idx < 128 * 512 + 256 * 128) {
        int idx2 = idx - 128 * 512;
        int j = idx2 >> 7;
        int a = idx2 & 127;
        g_WnT[idx2] = to_tf32(0.125f * Wn[a * 256 + j]);
    }
}

// ---------------------------------------------------------------------------
// gemm1: [B,256] x [256,128] twice.  grid.x==0: q = center@Wc^T -> g_Q (tf32)
//                                    grid.x==1: center_out -> out[:,0:128]
//   128x128 block tile, 8 warps (2x4), warp 64x32  (round-2 proven shape)
// ---------------------------------------------------------------------------
__global__ __launch_bounds__(256) void gemm1_kernel(const float* __restrict__ C,
                                                    const float* __restrict__ Wc,
                                                    const float* __restrict__ Wco,
                                                    float* __restrict__ out) {
    __shared__ float As[128 * 36];
    __shared__ float Bs[128 * 36];

    int tid = threadIdx.x;
    int warp = tid >> 5, lane = tid & 31;
    int mBase = blockIdx.y * 128;
    bool isQ = (blockIdx.x == 0);
    const float* W = isQ ? Wc : Wco;
    int warpM = warp >> 2, warpN = warp & 3;

    float acc[4][4][4];
#pragma unroll
    for (int a = 0; a < 4; a++)
#pragma unroll
        for (int b = 0; b < 4; b++)
#pragma unroll
            for (int c = 0; c < 4; c++) acc[a][b][c] = 0.f;

    int ldRow = tid >> 3;
    int ldCol = (tid & 7) << 2;

    for (int kk = 0; kk < 256; kk += 32) {
        __syncthreads();
#pragma unroll
        for (int seg = 0; seg < 4; seg++) {
            int r = ldRow + seg * 32;
            float4 va = *(const float4*)(C + (size_t)(mBase + r) * 256 + kk + ldCol);
            float4 vb = *(const float4*)(W + (size_t)r * 256 + kk + ldCol);
            va.x = to_tf32(va.x); va.y = to_tf32(va.y); va.z = to_tf32(va.z); va.w = to_tf32(va.w);
            vb.x = to_tf32(vb.x); vb.y = to_tf32(vb.y); vb.z = to_tf32(vb.z); vb.w = to_tf32(vb.w);
            *(float4*)(As + r * 36 + ldCol) = va;
            *(float4*)(Bs + r * 36 + ldCol) = vb;
        }
        __syncthreads();
#pragma unroll
        for (int k8 = 0; k8 < 4; k8++) {
            int kc = k8 * 8 + (lane & 3);
            uint32_t a[4][4], b[4][2];
#pragma unroll
            for (int mt = 0; mt < 4; mt++) {
                int r = warpM * 64 + mt * 16 + (lane >> 2);
                a[mt][0] = __float_as_uint(As[r * 36 + kc]);
                a[mt][1] = __float_as_uint(As[(r + 8) * 36 + kc]);
                a[mt][2] = __float_as_uint(As[r * 36 + kc + 4]);
                a[mt][3] = __float_as_uint(As[(r + 8) * 36 + kc + 4]);
            }
#pragma unroll
            for (int nt = 0; nt < 4; nt++) {
                int n = warpN * 32 + nt * 8 + (lane >> 2);
                b[nt][0] = __float_as_uint(Bs[n * 36 + kc]);
                b[nt][1] = __float_as_uint(Bs[n * 36 + kc + 4]);
            }
#pragma unroll
            for (int mt = 0; mt < 4; mt++)
#pragma unroll
                for (int nt = 0; nt < 4; nt++)
                    mma_tf32(acc[mt][nt], a[mt], b[nt]);
        }
    }

#pragma unroll
    for (int mt = 0; mt < 4; mt++) {
#pragma unroll
        for (int nt = 0; nt < 4; nt++) {
            int r0 = mBase + warpM * 64 + mt * 16 + (lane >> 2);
            int c0 = warpN * 32 + nt * 8 + ((lane & 3) << 1);
            if (isQ) {
                g_Q[(size_t)r0 * 128 + c0]           = to_tf32(acc[mt][nt][0]);
                g_Q[(size_t)r0 * 128 + c0 + 1]       = to_tf32(acc[mt][nt][1]);
                g_Q[(size_t)(r0 + 8) * 128 + c0]     = to_tf32(acc[mt][nt][2]);
                g_Q[(size_t)(r0 + 8) * 128 + c0 + 1] = to_tf32(acc[mt][nt][3]);
            } else {
                out[(size_t)r0 * 256 + c0]           = acc[mt][nt][0];
                out[(size_t)r0 * 256 + c0 + 1]       = acc[mt][nt][1];
                out[(size_t)(r0 + 8) * 256 + c0]     = acc[mt][nt][2];
                out[(size_t)(r0 + 8) * 256 + c0 + 1] = acc[mt][nt][3];
            }
        }
    }
}

// ---------------------------------------------------------------------------
// attn: 64 rows/block, 8 warps.
//   A2: P[64,512] = q @ WnT (per head, K=64), full-width N=128 tiles
//   B : attention, 6-deep continuous cp.async ring (8 rows/warp)
//   C : out[:,128:256] = mixed[64,512] @ Mcat^T
// smem: Pbuf[64][516] | region shared by (qs[64][132]+Bs[128][36]) / ring(8w x 6 x 256)
// ---------------------------------------------------------------------------
#define PB_STRIDE 516
#define RING_OFF  (64 * PB_STRIDE)            // 33024
#define QS_OFF    RING_OFF
#define QS_STRIDE 132
#define BS_OFF    (RING_OFF + 64 * QS_STRIDE) // 41472
#define BS_STRIDE 36
#define SMEM_FLOATS (BS_OFF + 128 * BS_STRIDE) // 46080
#define SMEM_BYTES  (SMEM_FLOATS * 4)          // 184320

__global__ __launch_bounds__(256, 1) void attn_kernel(const float* __restrict__ NBp,
                                                      const float* __restrict__ EW,
                                                      float* __restrict__ out) {
    extern __shared__ float sm[];
    int tid = threadIdx.x;
    int warp = tid >> 5, lane = tid & 31;
    int rowBase = blockIdx.x * 64;
    int warpM = warp >> 2, warpN = warp & 3;

    float* qs   = sm + QS_OFF;
    float* Bs   = sm + BS_OFF;
    float* ring = sm + RING_OFF + warp * (6 * 256);

    // ---- load q tile [64,128] (already tf32) ----
    for (int i = tid; i < 2048; i += 256) {
        int r = i >> 5, c4 = i & 31;
        cp16(qs + r * QS_STRIDE + c4 * 4, g_Q + (size_t)(rowBase + r) * 128 + c4 * 4);
    }
    cp_commit();
    asm volatile("cp.async.wait_group 0;" ::: "memory");
    __syncthreads();

    // ================= A2: P = q @ WnT =================
    for (int h = 0; h < 2; h++) {
        for (int nc = 0; nc < 2; nc++) {
            float acc[2][4][4];
#pragma unroll
            for (int a = 0; a < 2; a++)
#pragma unroll
                for (int b = 0; b < 4; b++)
#pragma unroll
                    for (int c = 0; c < 4; c++) acc[a][b][c] = 0.f;

#pragma unroll
            for (int kk = 0; kk < 64; kk += 32) {
                __syncthreads();
                {
                    int r = tid >> 3, c4 = (tid & 7) << 2;
#pragma unroll
                    for (int seg = 0; seg < 4; seg++) {
                        int rr2 = r + seg * 32;
                        float4 v = *(const float4*)(g_WnT + (size_t)(nc * 128 + rr2) * 128 + h * 64 + kk + c4);
                        *(float4*)(Bs + rr2 * BS_STRIDE + c4) = v;
                    }
                }
                __syncthreads();
#pragma unroll
                for (int k8 = 0; k8 < 4; k8++) {
                    int kc = k8 * 8 + (lane & 3);
                    uint32_t b[4][2];
#pragma unroll
                    for (int nt = 0; nt < 4; nt++) {
                        int n = warpN * 32 + nt * 8 + (lane >> 2);
                        b[nt][0] = __float_as_uint(Bs[n * BS_STRIDE + kc]);
                        b[nt][1] = __float_as_uint(Bs[n * BS_STRIDE + kc + 4]);
                    }
#pragma unroll
                    for (int mt = 0; mt < 2; mt++) {
                        int rA = warpM * 32 + mt * 16 + (lane >> 2);
                        uint32_t a[4];
                        a[0] = __float_as_uint(qs[rA * QS_STRIDE + h * 64 + kk + kc]);
                        a[1] = __float_as_uint(qs[(rA + 8) * QS_STRIDE + h * 64 + kk + kc]);
                        a[2] = __float_as_uint(qs[rA * QS_STRIDE + h * 64 + kk + kc + 4]);
                        a[3] = __float_as_uint(qs[(rA + 8) * QS_STRIDE + h * 64 + kk + kc + 4]);
#pragma unroll
                        for (int nt = 0; nt < 4; nt++) mma_tf32(acc[mt][nt], a, b[nt]);
                    }
                }
            }
#pragma unroll
            for (int mt = 0; mt < 2; mt++) {
#pragma unroll
                for (int nt = 0; nt < 4; nt++) {
                    int row = warpM * 32 + mt * 16 + (lane >> 2);
                    int col = h * 256 + nc * 128 + warpN * 32 + nt * 8 + ((lane & 3) << 1);
                    sm[row * PB_STRIDE + col]           = acc[mt][nt][0];
                    sm[row * PB_STRIDE + col + 1]       = acc[mt][nt][1];
                    sm[(row + 8) * PB_STRIDE + col]     = acc[mt][nt][2];
                    sm[(row + 8) * PB_STRIDE + col + 1] = acc[mt][nt][3];
                }
            }
        }
    }
    __syncthreads();   // P ready; qs/Bs dead -> ring region free

    // ================= Phase B: attention, continuous 6-deep ring =================
    {
        const float* base = NBp + (size_t)(rowBase + warp * 8) * 4096;
#pragma unroll
        for (int t = 0; t < 6; t++) {
            float* dst = ring + t * 256 + lane * 8;
            cp16(dst, base + t * 256 + lane * 8);
            cp16(dst + 4, base + t * 256 + lane * 8 + 4);
            cp_commit();
        }

        int slot = 0;
        for (int r = 0; r < 8; r++) {
            int lrow = warp * 8 + r;
            float* prow = sm + lrow * PB_STRIDE;
            float4 t0 = *(const float4*)(prow + lane * 8);
            float4 t1 = *(const float4*)(prow + lane * 8 + 4);
            float4 t2 = *(const float4*)(prow + 256 + lane * 8);
            float4 t3 = *(const float4*)(prow + 256 + lane * 8 + 4);
            float P0[8] = {t0.x, t0.y, t0.z, t0.w, t1.x, t1.y, t1.z, t1.w};
            float P1[8] = {t2.x, t2.y, t2.z, t2.w, t3.x, t3.y, t3.z, t3.w};
            float ewv = (lane < 16) ? EW[(size_t)(rowBase + lrow) * 16 + lane] : 0.f;

            float acc0[8], acc1[8];
#pragma unroll
            for (int j = 0; j < 8; j++) { acc0[j] = 0.f; acc1[j] = 0.f; }
            float l0 = 0.f, l1 = 0.f;

#pragma unroll
            for (int k = 0; k < 16; k++) {
                asm volatile("cp.async.wait_group 5;" ::: "memory");
                const float* src = ring + slot * 256 + lane * 8;
                float4 v0 = *(const float4*)(src);
                float4 v1 = *(const float4*)(src + 4);
                float nv[8] = {v0.x, v0.y, v0.z, v0.w, v1.x, v1.y, v1.z, v1.w};

                float s0 = 0.f, s1 = 0.f;
#pragma unroll
                for (int j = 0; j < 8; j++) { s0 += nv[j] * P0[j]; s1 += nv[j] * P1[j]; }
#pragma unroll
                for (int off = 16; off; off >>= 1) {
                    s0 += __shfl_xor_sync(0xffffffffu, s0, off);
                    s1 += __shfl_xor_sync(0xffffffffu, s1, off);
                }
                float e = __shfl_sync(0xffffffffu, ewv, k);
                float w0 = __expf(s0 + e);   // scores bounded: max-free softmax safe
                float w1 = __expf(s1 + e);
                l0 += w0; l1 += w1;
#pragma unroll
                for (int j = 0; j < 8; j++) { acc0[j] += w0 * nv[j]; acc1[j] += w1 * nv[j]; }

                int tn = r * 16 + k + 6;
                if (tn < 128) {
                    const float* nsrc = NBp + (size_t)(rowBase + warp * 8 + (tn >> 4)) * 4096
                                        + (tn & 15) * 256 + lane * 8;
                    float* dst = ring + slot * 256 + lane * 8;
                    cp16(dst, nsrc);
                    cp16(dst + 4, nsrc + 4);
                }
                cp_commit();
                slot = (slot == 5) ? 0 : slot + 1;
            }

            float i0 = 1.f / l0, i1 = 1.f / l1;
            float4 o;
            o.x = to_tf32(acc0[0] * i0); o.y = to_tf32(acc0[1] * i0);
            o.z = to_tf32(acc0[2] * i0); o.w = to_tf32(acc0[3] * i0);
            *(float4*)(prow + lane * 8) = o;
            o.x = to_tf32(acc0[4] * i0); o.y = to_tf32(acc0[5] * i0);
            o.z = to_tf32(acc0[6] * i0); o.w = to_tf32(acc0[7] * i0);
            *(float4*)(prow + lane * 8 + 4) = o;
            o.x = to_tf32(acc1[0] * i1); o.y = to_tf32(acc1[1] * i1);
            o.z = to_tf32(acc1[2] * i1); o.w = to_tf32(acc1[3] * i1);
            *(float4*)(prow + 256 + lane * 8) = o;
            o.x = to_tf32(acc1[4] * i1); o.y = to_tf32(acc1[5] * i1);
            o.z = to_tf32(acc1[6] * i1); o.w = to_tf32(acc1[7] * i1);
            *(float4*)(prow + 256 + lane * 8 + 4) = o;
        }
    }
    __syncthreads();   // mixed ready; ring dead

    // ================= Phase C: out[:,128:256] = mixed @ Mcat^T =================
    {
        float acc2[2][4][4];
#pragma unroll
        for (int a = 0; a < 2; a++)
#pragma unroll
            for (int b = 0; b < 4; b++)
#pragma unroll
                for (int c = 0; c < 4; c++) acc2[a][b][c] = 0.f;

        for (int kk = 0; kk < 512; kk += 32) {
            __syncthreads();
            {
                int r = tid >> 3, c4 = (tid & 7) << 2;
#pragma unroll
                for (int seg = 0; seg < 4; seg++) {
                    int rr2 = r + seg * 32;
                    float4 v = *(const float4*)(g_Mcat + (size_t)rr2 * 512 + kk + c4);
                    *(float4*)(Bs + rr2 * BS_STRIDE + c4) = v;
                }
            }
            __syncthreads();
#pragma unroll
            for (int k8 = 0; k8 < 4; k8++) {
                int kc = k8 * 8 + (lane & 3);
                uint32_t b[4][2];
#pragma unroll
                for (int nt = 0; nt < 4; nt++) {
                    int n = warpN * 32 + nt * 8 + (lane >> 2);
                    b[nt][0] = __float_as_uint(Bs[n * BS_STRIDE + kc]);
                    b[nt][1] = __float_as_uint(Bs[n * BS_STRIDE + kc + 4]);
                }
#pragma unroll
                for (int mt = 0; mt < 2; mt++) {
                    int rA = warpM * 32 + mt * 16 + (lane >> 2);
                    uint32_t a[4];
                    a[0] = __float_as_uint(sm[rA * PB_STRIDE + kk + kc]);
                    a[1] = __float_as_uint(sm[(rA + 8) * PB_STRIDE + kk + kc]);
                    a[2] = __float_as_uint(sm[rA * PB_STRIDE + kk + kc + 4]);
                    a[3] = __float_as_uint(sm[(rA + 8) * PB_STRIDE + kk + kc + 4]);
#pragma unroll
                    for (int nt = 0; nt < 4; nt++) mma_tf32(acc2[mt][nt], a, b[nt]);
                }
            }
        }

#pragma unroll
        for (int mt = 0; mt < 2; mt++) {
#pragma unroll
            for (int nt = 0; nt < 4; nt++) {
                int r0 = rowBase + warpM * 32 + mt * 16 + (lane >> 2);
                int c0 = 128 + warpN * 32 + nt * 8 + ((lane & 3) << 1);
                out[(size_t)r0 * 256 + c0]           = acc2[mt][nt][0];
                out[(size_t)r0 * 256 + c0 + 1]       = acc2[mt][nt][1];
                out[(size_t)(r0 + 8) * 256 + c0]     = acc2[mt][nt][2];
                out[(size_t)(r0 + 8) * 256 + c0 + 1] = acc2[mt][nt][3];
            }
        }
    }
}

// ---------------------------------------------------------------------------
extern "C" void kernel_launch(void* const* d_in, const int* in_sizes, int n_in,
                              void* d_out, int out_size) {
    const float* center   = (const float*)d_in[0];
    const float* neighbor = (const float*)d_in[1];
    const float* edge     = (const float*)d_in[2];
    const float* Wc       = (const float*)d_in[3];
    const float* Wn       = (const float*)d_in[4];
    const float* Wv       = (const float*)d_in[5];
    const float* Wout     = (const float*)d_in[6];
    const float* Wco      = (const float*)d_in[7];
    float* out = (float*)d_out;

    cudaFuncSetAttribute(attn_kernel, cudaFuncAttributeMaxDynamicSharedMemorySize, SMEM_BYTES);

    prep_kernel<<<(128 * 512 + 256 * 128 + 255) / 256, 256>>>(Wn, Wv, Wout);
    gemm1_kernel<<<dim3(2, NB_B / 128), 256>>>(center, Wc, Wco, out);
    attn_kernel<<<NB_B / 64, 256, SMEM_BYTES>>>(neighbor, edge, out);
}

// round 5
// speedup vs baseline: 2.1618x; 1.1104x over previous
#include <cuda_runtime.h>
#include <cstdint>

// B=131072, IN_DIM=256, K=16, H=2, ATTN_DIM=64
#define NB_B 131072

// device scratch
__device__ float g_Mcat[128 * 512];          // tf32: Mcat[o][h*256+i]
__device__ float g_WnT[256 * 128];           // tf32: 0.125*Wn^T  [j][h*64+a]
__device__ float g_Q[(size_t)NB_B * 128];    // tf32: q = center @ Wc^T

__device__ __forceinline__ float to_tf32(float x) {
    uint32_t u;
    asm("cvt.rna.tf32.f32 %0, %1;" : "=r"(u) : "f"(x));
    return __uint_as_float(u);
}

__device__ __forceinline__ void mma_tf32(float* c, const uint32_t* a, const uint32_t* b) {
    asm volatile(
        "mma.sync.aligned.m16n8k8.row.col.f32.tf32.tf32.f32 "
        "{%0,%1,%2,%3}, {%4,%5,%6,%7}, {%8,%9}, {%0,%1,%2,%3};"
        : "+f"(c[0]), "+f"(c[1]), "+f"(c[2]), "+f"(c[3])
        : "r"(a[0]), "r"(a[1]), "r"(a[2]), "r"(a[3]), "r"(b[0]), "r"(b[1]));
}

__device__ __forceinline__ void cp16(float* dst, const float* src) {
    uint32_t d = (uint32_t)__cvta_generic_to_shared(dst);
    asm volatile("cp.async.cg.shared.global [%0], [%1], 16;" :: "r"(d), "l"(src));
}
__device__ __forceinline__ void cp_commit() { asm volatile("cp.async.commit_group;"); }

// ---------------------------------------------------------------------------
// prep: Mcat = Wout_h * Wv_h (tf32);  WnT = 0.125 * Wn^T (tf32)
// ---------------------------------------------------------------------------
__global__ void prep_kernel(const float* __restrict__ Wn, const float* __restrict__ Wv,
                            const float* __restrict__ Wout) {
    int idx = blockIdx.x * blockDim.x + threadIdx.x;
    if (idx < 128 * 512) {
        int o = idx >> 9;
        int c = idx & 511;
        int h = c >> 8;
        int i = c & 255;
        float s = 0.f;
#pragma unroll 8
        for (int d = 0; d < 128; d++)
            s += Wout[o * 256 + h * 128 + d] * Wv[(h * 128 + d) * 256 + i];
        g_Mcat[idx] = to_tf32(s);
    } else if (idx < 128 * 512 + 256 * 128) {
        int idx2 = idx - 128 * 512;
        int j = idx2 >> 7;
        int a = idx2 & 127;
        g_WnT[idx2] = to_tf32(0.125f * Wn[a * 256 + j]);
    }
}

// ---------------------------------------------------------------------------
// gemm1: [B,256] x [256,128] twice.  grid.x==0: q -> g_Q (tf32)
//                                    grid.x==1: center_out -> out[:,0:128]
// ---------------------------------------------------------------------------
__global__ __launch_bounds__(256) void gemm1_kernel(const float* __restrict__ C,
                                                    const float* __restrict__ Wc,
                                                    const float* __restrict__ Wco,
                                                    float* __restrict__ out) {
    __shared__ float As[128 * 36];
    __shared__ float Bs[128 * 36];

    int tid = threadIdx.x;
    int warp = tid >> 5, lane = tid & 31;
    int mBase = blockIdx.y * 128;
    bool isQ = (blockIdx.x == 0);
    const float* W = isQ ? Wc : Wco;
    int warpM = warp >> 2, warpN = warp & 3;

    float acc[4][4][4];
#pragma unroll
    for (int a = 0; a < 4; a++)
#pragma unroll
        for (int b = 0; b < 4; b++)
#pragma unroll
            for (int c = 0; c < 4; c++) acc[a][b][c] = 0.f;

    int ldRow = tid >> 3;
    int ldCol = (tid & 7) << 2;

    for (int kk = 0; kk < 256; kk += 32) {
        __syncthreads();
#pragma unroll
        for (int seg = 0; seg < 4; seg++) {
            int r = ldRow + seg * 32;
            float4 va = *(const float4*)(C + (size_t)(mBase + r) * 256 + kk + ldCol);
            float4 vb = *(const float4*)(W + (size_t)r * 256 + kk + ldCol);
            va.x = to_tf32(va.x); va.y = to_tf32(va.y); va.z = to_tf32(va.z); va.w = to_tf32(va.w);
            vb.x = to_tf32(vb.x); vb.y = to_tf32(vb.y); vb.z = to_tf32(vb.z); vb.w = to_tf32(vb.w);
            *(float4*)(As + r * 36 + ldCol) = va;
            *(float4*)(Bs + r * 36 + ldCol) = vb;
        }
        __syncthreads();
#pragma unroll
        for (int k8 = 0; k8 < 4; k8++) {
            int kc = k8 * 8 + (lane & 3);
            uint32_t a[4][4], b[4][2];
#pragma unroll
            for (int mt = 0; mt < 4; mt++) {
                int r = warpM * 64 + mt * 16 + (lane >> 2);
                a[mt][0] = __float_as_uint(As[r * 36 + kc]);
                a[mt][1] = __float_as_uint(As[(r + 8) * 36 + kc]);
                a[mt][2] = __float_as_uint(As[r * 36 + kc + 4]);
                a[mt][3] = __float_as_uint(As[(r + 8) * 36 + kc + 4]);
            }
#pragma unroll
            for (int nt = 0; nt < 4; nt++) {
                int n = warpN * 32 + nt * 8 + (lane >> 2);
                b[nt][0] = __float_as_uint(Bs[n * 36 + kc]);
                b[nt][1] = __float_as_uint(Bs[n * 36 + kc + 4]);
            }
#pragma unroll
            for (int mt = 0; mt < 4; mt++)
#pragma unroll
                for (int nt = 0; nt < 4; nt++)
                    mma_tf32(acc[mt][nt], a[mt], b[nt]);
        }
    }

#pragma unroll
    for (int mt = 0; mt < 4; mt++) {
#pragma unroll
        for (int nt = 0; nt < 4; nt++) {
            int r0 = mBase + warpM * 64 + mt * 16 + (lane >> 2);
            int c0 = warpN * 32 + nt * 8 + ((lane & 3) << 1);
            if (isQ) {
                g_Q[(size_t)r0 * 128 + c0]           = to_tf32(acc[mt][nt][0]);
                g_Q[(size_t)r0 * 128 + c0 + 1]       = to_tf32(acc[mt][nt][1]);
                g_Q[(size_t)(r0 + 8) * 128 + c0]     = to_tf32(acc[mt][nt][2]);
                g_Q[(size_t)(r0 + 8) * 128 + c0 + 1] = to_tf32(acc[mt][nt][3]);
            } else {
                out[(size_t)r0 * 256 + c0]           = acc[mt][nt][0];
                out[(size_t)r0 * 256 + c0 + 1]       = acc[mt][nt][1];
                out[(size_t)(r0 + 8) * 256 + c0]     = acc[mt][nt][2];
                out[(size_t)(r0 + 8) * 256 + c0 + 1] = acc[mt][nt][3];
            }
        }
    }
}

// ---------------------------------------------------------------------------
// attn: 32 rows/block, 8 warps, 2 BLOCKS/SM (the round-5 change).
//   A2: P[32,512] = q @ WnT (per head, K=64)
//   B : attention, 5-deep continuous cp.async ring (4 rows/warp)
//   C : out[:,128:256] = mixed[32,512] @ Mcat^T
// smem (floats): Pbuf[32][516]=16512 | ring 8w x 5 x 256 = 10240
//                (qs[32][132]=4224 + Bs[128][36]=4608 overlay the ring region)
// total = 26752 floats = 104.5 KB -> 2 blocks/SM (209 KB < 228 KB)
// ---------------------------------------------------------------------------
#define PB_STRIDE 516
#define RING_OFF  (32 * PB_STRIDE)            // 16512
#define QS_OFF    RING_OFF
#define QS_STRIDE 132
#define BS_OFF    (RING_OFF + 32 * QS_STRIDE) // 20736
#define BS_STRIDE 36
#define SMEM_FLOATS (RING_OFF + 8 * 5 * 256)  // 26752
#define SMEM_BYTES  (SMEM_FLOATS * 4)         // 107008

__global__ __launch_bounds__(256, 2) void attn_kernel(const float* __restrict__ NBp,
                                                      const float* __restrict__ EW,
                                                      float* __restrict__ out) {
    extern __shared__ float sm[];
    int tid = threadIdx.x;
    int warp = tid >> 5, lane = tid & 31;
    int rowBase = blockIdx.x * 32;
    int warpM = warp >> 2, warpN = warp & 3;

    float* qs   = sm + QS_OFF;
    float* Bs   = sm + BS_OFF;
    float* ring = sm + RING_OFF + warp * (5 * 256);

    // ---- load q tile [32,128] (already tf32) ----
    for (int i = tid; i < 1024; i += 256) {
        int r = i >> 5, c4 = i & 31;
        cp16(qs + r * QS_STRIDE + c4 * 4, g_Q + (size_t)(rowBase + r) * 128 + c4 * 4);
    }
    cp_commit();
    asm volatile("cp.async.wait_group 0;" ::: "memory");
    __syncthreads();

    int rA = warpM * 16 + (lane >> 2);

    // ================= A2: P = q @ WnT =================
    for (int h = 0; h < 2; h++) {
        for (int nc = 0; nc < 2; nc++) {
            float acc[4][4];
#pragma unroll
            for (int b = 0; b < 4; b++)
#pragma unroll
                for (int c = 0; c < 4; c++) acc[b][c] = 0.f;

#pragma unroll
            for (int kk = 0; kk < 64; kk += 32) {
                __syncthreads();
                {
                    int r = tid >> 3, c4 = (tid & 7) << 2;
#pragma unroll
                    for (int seg = 0; seg < 4; seg++) {
                        int rr2 = r + seg * 32;
                        float4 v = *(const float4*)(g_WnT + (size_t)(nc * 128 + rr2) * 128 + h * 64 + kk + c4);
                        *(float4*)(Bs + rr2 * BS_STRIDE + c4) = v;
                    }
                }
                __syncthreads();
#pragma unroll
                for (int k8 = 0; k8 < 4; k8++) {
                    int kc = k8 * 8 + (lane & 3);
                    uint32_t a[4], b[4][2];
                    a[0] = __float_as_uint(qs[rA * QS_STRIDE + h * 64 + kk + kc]);
                    a[1] = __float_as_uint(qs[(rA + 8) * QS_STRIDE + h * 64 + kk + kc]);
                    a[2] = __float_as_uint(qs[rA * QS_STRIDE + h * 64 + kk + kc + 4]);
                    a[3] = __float_as_uint(qs[(rA + 8) * QS_STRIDE + h * 64 + kk + kc + 4]);
#pragma unroll
                    for (int nt = 0; nt < 4; nt++) {
                        int n = warpN * 32 + nt * 8 + (lane >> 2);
                        b[nt][0] = __float_as_uint(Bs[n * BS_STRIDE + kc]);
                        b[nt][1] = __float_as_uint(Bs[n * BS_STRIDE + kc + 4]);
                        mma_tf32(acc[nt], a, b[nt]);
                    }
                }
            }
#pragma unroll
            for (int nt = 0; nt < 4; nt++) {
                int col = h * 256 + nc * 128 + warpN * 32 + nt * 8 + ((lane & 3) << 1);
                sm[rA * PB_STRIDE + col]           = acc[nt][0];
                sm[rA * PB_STRIDE + col + 1]       = acc[nt][1];
                sm[(rA + 8) * PB_STRIDE + col]     = acc[nt][2];
                sm[(rA + 8) * PB_STRIDE + col + 1] = acc[nt][3];
            }
        }
    }
    __syncthreads();   // P ready; qs/Bs dead -> ring region free

    // ================= Phase B: attention, continuous 5-deep ring =================
    {
        const float* base = NBp + (size_t)(rowBase + warp * 4) * 4096;
#pragma unroll
        for (int t = 0; t < 5; t++) {
            float* dst = ring + t * 256 + lane * 8;
            cp16(dst, base + t * 256 + lane * 8);
            cp16(dst + 4, base + t * 256 + lane * 8 + 4);
            cp_commit();
        }

        int slot = 0;
        for (int r = 0; r < 4; r++) {
            int lrow = warp * 4 + r;
            float* prow = sm + lrow * PB_STRIDE;
            float4 t0 = *(const float4*)(prow + lane * 8);
            float4 t1 = *(const float4*)(prow + lane * 8 + 4);
            float4 t2 = *(const float4*)(prow + 256 + lane * 8);
            float4 t3 = *(const float4*)(prow + 256 + lane * 8 + 4);
            float P0[8] = {t0.x, t0.y, t0.z, t0.w, t1.x, t1.y, t1.z, t1.w};
            float P1[8] = {t2.x, t2.y, t2.z, t2.w, t3.x, t3.y, t3.z, t3.w};
            float ewv = (lane < 16) ? EW[(size_t)(rowBase + lrow) * 16 + lane] : 0.f;

            float acc0[8], acc1[8];
#pragma unroll
            for (int j = 0; j < 8; j++) { acc0[j] = 0.f; acc1[j] = 0.f; }
            float l0 = 0.f, l1 = 0.f;

#pragma unroll
            for (int k = 0; k < 16; k++) {
                asm volatile("cp.async.wait_group 4;" ::: "memory");
                const float* src = ring + slot * 256 + lane * 8;
                float4 v0 = *(const float4*)(src);
                float4 v1 = *(const float4*)(src + 4);
                float nv[8] = {v0.x, v0.y, v0.z, v0.w, v1.x, v1.y, v1.z, v1.w};

                float s0 = 0.f, s1 = 0.f;
#pragma unroll
                for (int j = 0; j < 8; j++) { s0 += nv[j] * P0[j]; s1 += nv[j] * P1[j]; }
#pragma unroll
                for (int off = 16; off; off >>= 1) {
                    s0 += __shfl_xor_sync(0xffffffffu, s0, off);
                    s1 += __shfl_xor_sync(0xffffffffu, s1, off);
                }
                float e = __shfl_sync(0xffffffffu, ewv, k);
                float w0 = __expf(s0 + e);   // scores bounded: max-free softmax safe
                float w1 = __expf(s1 + e);
                l0 += w0; l1 += w1;
#pragma unroll
                for (int j = 0; j < 8; j++) { acc0[j] += w0 * nv[j]; acc1[j] += w1 * nv[j]; }

                int tn = r * 16 + k + 5;
                if (tn < 64) {
                    const float* nsrc = NBp + (size_t)(rowBase + warp * 4 + (tn >> 4)) * 4096
                                        + (tn & 15) * 256 + lane * 8;
                    float* dst = ring + slot * 256 + lane * 8;
                    cp16(dst, nsrc);
                    cp16(dst + 4, nsrc + 4);
                }
                cp_commit();
                slot = (slot == 4) ? 0 : slot + 1;
            }

            float i0 = 1.f / l0, i1 = 1.f / l1;
            float4 o;
            o.x = to_tf32(acc0[0] * i0); o.y = to_tf32(acc0[1] * i0);
            o.z = to_tf32(acc0[2] * i0); o.w = to_tf32(acc0[3] * i0);
            *(float4*)(prow + lane * 8) = o;
            o.x = to_tf32(acc0[4] * i0); o.y = to_tf32(acc0[5] * i0);
            o.z = to_tf32(acc0[6] * i0); o.w = to_tf32(acc0[7] * i0);
            *(float4*)(prow + lane * 8 + 4) = o;
            o.x = to_tf32(acc1[0] * i1); o.y = to_tf32(acc1[1] * i1);
            o.z = to_tf32(acc1[2] * i1); o.w = to_tf32(acc1[3] * i1);
            *(float4*)(prow + 256 + lane * 8) = o;
            o.x = to_tf32(acc1[4] * i1); o.y = to_tf32(acc1[5] * i1);
            o.z = to_tf32(acc1[6] * i1); o.w = to_tf32(acc1[7] * i1);
            *(float4*)(prow + 256 + lane * 8 + 4) = o;
        }
    }
    __syncthreads();   // mixed ready; ring dead

    // ================= Phase C: out[:,128:256] = mixed @ Mcat^T =================
    {
        float acc2[4][4];
#pragma unroll
        for (int b = 0; b < 4; b++)
#pragma unroll
            for (int c = 0; c < 4; c++) acc2[b][c] = 0.f;

        for (int kk = 0; kk < 512; kk += 32) {
            __syncthreads();
            {
                int r = tid >> 3, c4 = (tid & 7) << 2;
#pragma unroll
                for (int seg = 0; seg < 4; seg++) {
                    int rr2 = r + seg * 32;
                    float4 v = *(const float4*)(g_Mcat + (size_t)rr2 * 512 + kk + c4);
                    *(float4*)(Bs + rr2 * BS_STRIDE + c4) = v;
                }
            }
            __syncthreads();
#pragma unroll
            for (int k8 = 0; k8 < 4; k8++) {
                int kc = k8 * 8 + (lane & 3);
                uint32_t a[4], b[4][2];
                a[0] = __float_as_uint(sm[rA * PB_STRIDE + kk + kc]);
                a[1] = __float_as_uint(sm[(rA + 8) * PB_STRIDE + kk + kc]);
                a[2] = __float_as_uint(sm[rA * PB_STRIDE + kk + kc + 4]);
                a[3] = __float_as_uint(sm[(rA + 8) * PB_STRIDE + kk + kc + 4]);
#pragma unroll
                for (int nt = 0; nt < 4; nt++) {
                    int n = warpN * 32 + nt * 8 + (lane >> 2);
                    b[nt][0] = __float_as_uint(Bs[n * BS_STRIDE + kc]);
                    b[nt][1] = __float_as_uint(Bs[n * BS_STRIDE + kc + 4]);
                    mma_tf32(acc2[nt], a, b[nt]);
                }
            }
        }

#pragma unroll
        for (int nt = 0; nt < 4; nt++) {
            int r0 = rowBase + rA;
            int c0 = 128 + warpN * 32 + nt * 8 + ((lane & 3) << 1);
            out[(size_t)r0 * 256 + c0]           = acc2[nt][0];
            out[(size_t)r0 * 256 + c0 + 1]       = acc2[nt][1];
            out[(size_t)(r0 + 8) * 256 + c0]     = acc2[nt][2];
            out[(size_t)(r0 + 8) * 256 + c0 + 1] = acc2[nt][3];
        }
    }
}

// ---------------------------------------------------------------------------
extern "C" void kernel_launch(void* const* d_in, const int* in_sizes, int n_in,
                              void* d_out, int out_size) {
    const float* center   = (const float*)d_in[0];
    const float* neighbor = (const float*)d_in[1];
    const float* edge     = (const float*)d_in[2];
    const float* Wc       = (const float*)d_in[3];
    const float* Wn       = (const float*)d_in[4];
    const float* Wv       = (const float*)d_in[5];
    const float* Wout     = (const float*)d_in[6];
    const float* Wco      = (const float*)d_in[7];
    float* out = (float*)d_out;

    cudaFuncSetAttribute(attn_kernel, cudaFuncAttributeMaxDynamicSharedMemorySize, SMEM_BYTES);

    prep_kernel<<<(128 * 512 + 256 * 128 + 255) / 256, 256>>>(Wn, Wv, Wout);
    gemm1_kernel<<<dim3(2, NB_B / 128), 256>>>(center, Wc, Wco, out);
    attn_kernel<<<NB_B / 32, 256, SMEM_BYTES>>>(neighbor, edge, out);
}